// round 8
// baseline (speedup 1.0000x reference)
#include <cuda_runtime.h>
#include <cuda_bf16.h>
#include <cstdint>

#define VOCAB 10000
#define EMBED 100
#define SEQ   80
#define UNITS 64
#define BATCH 16384
#define MROWS 128          // batch rows per CTA
#define XS    68           // xproj smem row stride (floats)
#define TKS   81           // token smem row stride (ints)

// xproj[v][u] = b1[u] + emb[v,:] @ Wx1[:,u]   (fp32, 2.56 MB, L2-resident)
__device__ float g_xproj[VOCAB * UNITS];

// ---------------------------------------------------------------------------
// helpers
// ---------------------------------------------------------------------------
__device__ __forceinline__ uint32_t smem_u32(const void* p) {
    uint32_t a;
    asm("{ .reg .u64 t; cvta.to.shared.u64 t, %1; cvt.u32.u64 %0, t; }" : "=r"(a) : "l"(p));
    return a;
}
#define SWZ(off) ((uint32_t)(off) ^ ((((uint32_t)(off)) >> 3) & 0x70))

__device__ __forceinline__ float tanh_fast(float x) {
    float r; asm("tanh.approx.f32 %0, %1;" : "=f"(r) : "f"(x)); return r;
}
__device__ __forceinline__ uint32_t pack_bf16(float lo, float hi) {
    uint32_t r; asm("cvt.rn.bf16x2.f32 %0, %1, %2;" : "=r"(r) : "f"(hi), "f"(lo)); return r;
}
__device__ __forceinline__ float2 unpk_bf16(uint32_t u) {
    __nv_bfloat162 b = *reinterpret_cast<__nv_bfloat162*>(&u);
    return __bfloat1622float2(b);
}

// LDSM: volatile (order pinned vs cp.async) but NO memory clobber —
// surrounding FP code may be scheduled around it.
#define LDSM_X4(r0, r1, r2, r3, addr)                                       \
    asm volatile("ldmatrix.sync.aligned.m8n8.x4.shared.b16 {%0,%1,%2,%3}, [%4];" \
                 : "=r"(r0), "=r"(r1), "=r"(r2), "=r"(r3) : "r"(addr))

// MMA: NON-volatile pure register op — ptxas is free to interleave it with
// MUFU/FADD/CVT streams. Dependencies are fully carried by operands.
#define MMA_BF16(ac, A, b0, b1)                                             \
    asm("mma.sync.aligned.m16n8k16.row.col.f32.bf16.bf16.f32 "              \
        "{%0,%1,%2,%3}, {%4,%5,%6,%7}, {%8,%9}, {%0,%1,%2,%3};"             \
        : "+f"((ac)[0]), "+f"((ac)[1]), "+f"((ac)[2]), "+f"((ac)[3])        \
        : "r"((A)[0]), "r"((A)[1]), "r"((A)[2]), "r"((A)[3]),               \
          "r"(b0), "r"(b1))

#define CP_ASYNC_8(dst, src)                                                \
    asm volatile("cp.async.ca.shared.global [%0], [%1], 8;"                 \
                 :: "r"(dst), "l"(src) : "memory")
#define CP_COMMIT()  asm volatile("cp.async.commit_group;" ::: "memory")
#define CP_WAIT1()   asm volatile("cp.async.wait_group 1;" ::: "memory")

// ---------------------------------------------------------------------------
// Kernel A: build xproj table
// ---------------------------------------------------------------------------
__global__ void build_xproj_kernel(const float* __restrict__ emb,
                                   const float* __restrict__ Wx1,
                                   const float* __restrict__ b1) {
    __shared__ float se[4 * EMBED];
    const int v0  = blockIdx.x * 4;
    const int tid = threadIdx.x;
    for (int i = tid; i < 4 * EMBED; i += 256)
        se[i] = emb[v0 * EMBED + i];
    __syncthreads();
    const int vl = tid >> 6;
    const int u  = tid & 63;
    const float* er = se + vl * EMBED;
    float a0 = 0.f, a1 = 0.f;
#pragma unroll
    for (int e = 0; e < EMBED; e += 2) {
        a0 += er[e]     * Wx1[e * UNITS + u];
        a1 += er[e + 1] * Wx1[(e + 1) * UNITS + u];
    }
    g_xproj[(v0 + vl) * UNITS + u] = b1[u] + a0 + a1;
}

// ---------------------------------------------------------------------------
// smem layout (byte offsets from 1024-aligned base)
// ---------------------------------------------------------------------------
#define OFF_W1   0                                  // Wh1^T [n][k] bf16 SW128, 8KB
#define OFF_XS0  8192                               // xproj buf 0: 128 x 68 fp32
#define OFF_XS1  (OFF_XS0 + MROWS * XS * 4)         // xproj buf 1
#define OFF_TOK  (OFF_XS1 + MROWS * XS * 4)         // 128 x 81 int
#define OFF_B2   (OFF_TOK + MROWS * TKS * 4)
#define OFF_WD   (OFF_B2 + 256)
#define SMEM_NEED (OFF_WD + 256 + 1024)

// ---------------------------------------------------------------------------
// Kernel B: 8 independent warps x 16 rows x full 64 cols.
// h1/h2 in registers (C-frag == A-frag identity). Zero barriers in loop.
// ---------------------------------------------------------------------------
__global__ void __launch_bounds__(256, 1)
rnn_mma_kernel(const int*   __restrict__ tokens,
               const float* __restrict__ Wh1,
               const float* __restrict__ Wx2,
               const float* __restrict__ Wh2,
               const float* __restrict__ b2,
               const float* __restrict__ Wd,
               const float* __restrict__ bd,
               float*       __restrict__ out) {
    extern __shared__ char dynsmem[];
    char* smem = (char*)(((uintptr_t)dynsmem + 1023) & ~(uintptr_t)1023);
    const uint32_t sb = smem_u32(smem);
    int*   stok = (int*)(smem + OFF_TOK);
    float* sB2  = (float*)(smem + OFF_B2);
    float* sWd  = (float*)(smem + OFF_WD);

    const int tid  = threadIdx.x;
    const int lane = tid & 31;
    const int wid  = tid >> 5;
    const int gid  = lane >> 2;
    const int tig  = lane & 3;
    const int wrow16 = wid * 16;
    const int m0   = blockIdx.x * MROWS;

    // ---- persistent B-fragments (full 64 cols): [nt][kt][2] ----
    uint32_t BX2[8][4][2], BH2[8][4][2];
#pragma unroll
    for (int nt = 0; nt < 8; nt++)
#pragma unroll
        for (int kt = 0; kt < 4; kt++) {
            const int n = nt * 8 + gid;
            const int k = kt * 16 + tig * 2;
            BX2[nt][kt][0] = pack_bf16(Wx2[k * 64 + n],       Wx2[(k + 1) * 64 + n]);
            BX2[nt][kt][1] = pack_bf16(Wx2[(k + 8) * 64 + n], Wx2[(k + 9) * 64 + n]);
            BH2[nt][kt][0] = pack_bf16(Wh2[k * 64 + n],       Wh2[(k + 1) * 64 + n]);
            BH2[nt][kt][1] = pack_bf16(Wh2[(k + 8) * 64 + n], Wh2[(k + 9) * 64 + n]);
        }

    // ---- init smem: Wh1^T tile [n][k] bf16 SW128, tokens, b2, Wd ----
    for (int i = tid; i < UNITS * UNITS; i += 256) {
        int n = i >> 6, k = i & 63;
        *(__nv_bfloat16*)(smem + OFF_W1 + SWZ(n * 128 + k * 2)) =
            __float2bfloat16(Wh1[k * 64 + n]);
    }
    {
        const int* gtok = tokens + m0 * SEQ;
        for (int i = tid; i < MROWS * SEQ; i += 256)
            stok[(i / SEQ) * TKS + (i % SEQ)] = gtok[i];
    }
    if (tid < UNITS) { sB2[tid] = b2[tid]; sWd[tid] = Wd[tid]; }
    __syncthreads();

    const uint32_t w1Base = sb + OFF_W1;
    const uint32_t bRow = (uint32_t)((((lane >> 4) << 3) | (lane & 7)));
    const uint32_t bKo  = (uint32_t)(((lane >> 3) & 1) << 3);
    const uint32_t xsLaneOff = (uint32_t)(wrow16 * XS * 4) + (uint32_t)(lane * 8);

    // h fragments (A-frag layout), h0 = 0
    uint32_t h1f[4][4], h2f[4][4];
#pragma unroll
    for (int kt = 0; kt < 4; kt++)
#pragma unroll
        for (int j = 0; j < 4; j++) { h1f[kt][j] = 0u; h2f[kt][j] = 0u; }

    float acc1[8][4], acc2[8][4];

    // ---- pre-loop: issue gather for t = 0 into buf 0 ----
    {
        int tokreg = 0;
        if (lane < 16) tokreg = stok[(wrow16 + lane) * TKS + 0];
        const uint32_t dst = sb + OFF_XS0 + xsLaneOff;
#pragma unroll
        for (int r = 0; r < 16; r++) {
            const int tok = __shfl_sync(0xffffffffu, tokreg, r);
            CP_ASYNC_8(dst + (uint32_t)(r * XS * 4), g_xproj + tok * UNITS + lane * 2);
        }
        CP_COMMIT();
    }

#pragma unroll 2
    for (int t = 0; t < SEQ; t++) {
        float* xs = (float*)(smem + ((t & 1) ? OFF_XS1 : OFF_XS0));

        // ---- prefetch gather for t+1 (clamped; depth-1 pipeline) ----
        {
            const int tn = (t + 1 < SEQ) ? t + 1 : SEQ - 1;
            int tokreg = 0;
            if (lane < 16) tokreg = stok[(wrow16 + lane) * TKS + tn];
            const uint32_t dst = sb + ((tn & 1) ? OFF_XS1 : OFF_XS0) + xsLaneOff;
#pragma unroll
            for (int r = 0; r < 16; r++) {
                const int tok = __shfl_sync(0xffffffffu, tokreg, r);
                CP_ASYNC_8(dst + (uint32_t)(r * XS * 4), g_xproj + tok * UNITS + lane * 2);
            }
            CP_COMMIT();
        }

        // ---- gemm1 (h1 @ Wh1, streamed B) interleaved with gemm2a (h2 @ Wh2) ----
#pragma unroll
        for (int nt = 0; nt < 8; nt++)
#pragma unroll
            for (int c = 0; c < 4; c++) { acc1[nt][c] = 0.f; acc2[nt][c] = 0.f; }
#pragma unroll
        for (int kt = 0; kt < 4; kt++) {
            uint32_t Bs[4][4];
#pragma unroll
            for (int np = 0; np < 4; np++)
                LDSM_X4(Bs[np][0], Bs[np][1], Bs[np][2], Bs[np][3],
                        w1Base + SWZ((np * 16 + bRow) * 128 + (kt * 16 + bKo) * 2));
#pragma unroll
            for (int nt = 0; nt < 8; nt++)
                MMA_BF16(acc2[nt], h2f[kt], BH2[nt][kt][0], BH2[nt][kt][1]);
#pragma unroll
            for (int np = 0; np < 4; np++) {
                MMA_BF16(acc1[2 * np],     h1f[kt], Bs[np][0], Bs[np][1]);
                MMA_BF16(acc1[2 * np + 1], h1f[kt], Bs[np][2], Bs[np][3]);
            }
        }

        CP_WAIT1();   // step-t rows landed (t+1's group may still fly)

        // ---- epi1 interleaved with gemm2b: per nt-pair a, tanh -> h1f[a],
        //      then immediately the 8 MMAs consuming h1f[a] ----
        const int r0 = wrow16 + gid;
#pragma unroll
        for (int a = 0; a < 4; a++) {
#pragma unroll
            for (int half = 0; half < 2; half++) {
                const int nt = 2 * a + half;
                const int col = nt * 8 + tig * 2;
                float2 xa = *(const float2*)(xs + r0 * XS + col);
                float2 xb = *(const float2*)(xs + (r0 + 8) * XS + col);
                float h0 = tanh_fast(acc1[nt][0] + xa.x);
                float h1 = tanh_fast(acc1[nt][1] + xa.y);
                float h2 = tanh_fast(acc1[nt][2] + xb.x);
                float h3 = tanh_fast(acc1[nt][3] + xb.y);
                h1f[a][half * 2 + 0] = pack_bf16(h0, h1);
                h1f[a][half * 2 + 1] = pack_bf16(h2, h3);
            }
#pragma unroll
            for (int nt = 0; nt < 8; nt++)
                MMA_BF16(acc2[nt], h1f[a], BX2[nt][a][0], BX2[nt][a][1]);
        }

        // ---- epi2: h2 = tanh(acc2 + b2) -> A-frags ----
#pragma unroll
        for (int nt = 0; nt < 8; nt++) {
            const int col = nt * 8 + tig * 2;
            float2 bb = *(const float2*)(sB2 + col);
            float h0 = tanh_fast(acc2[nt][0] + bb.x);
            float h1 = tanh_fast(acc2[nt][1] + bb.y);
            float h2 = tanh_fast(acc2[nt][2] + bb.x);
            float h3 = tanh_fast(acc2[nt][3] + bb.y);
            h2f[nt >> 1][(nt & 1) * 2 + 0] = pack_bf16(h0, h1);
            h2f[nt >> 1][(nt & 1) * 2 + 1] = pack_bf16(h2, h3);
        }
    }

    // ---- head: out = sigmoid(h2 . Wd + bd); reduce over tig group ----
    float z0 = 0.f, z1 = 0.f;
#pragma unroll
    for (int nt = 0; nt < 8; nt++) {
        const int col = nt * 8 + tig * 2;
        float2 wd = *(const float2*)(sWd + col);
        float2 a = unpk_bf16(h2f[nt >> 1][(nt & 1) * 2 + 0]);
        float2 b = unpk_bf16(h2f[nt >> 1][(nt & 1) * 2 + 1]);
        z0 += a.x * wd.x + a.y * wd.y;
        z1 += b.x * wd.x + b.y * wd.y;
    }
    z0 += __shfl_xor_sync(0xffffffffu, z0, 1);
    z0 += __shfl_xor_sync(0xffffffffu, z0, 2);
    z1 += __shfl_xor_sync(0xffffffffu, z1, 1);
    z1 += __shfl_xor_sync(0xffffffffu, z1, 2);
    if (tig == 0) {
        const float bd0 = bd[0];
        out[m0 + wrow16 + gid]     = 1.0f / (1.0f + __expf(-(z0 + bd0)));
        out[m0 + wrow16 + gid + 8] = 1.0f / (1.0f + __expf(-(z1 + bd0)));
    }
}

// ---------------------------------------------------------------------------
extern "C" void kernel_launch(void* const* d_in, const int* in_sizes, int n_in,
                              void* d_out, int out_size) {
    const int*   tokens = (const int*)  d_in[0];
    const float* emb    = (const float*)d_in[1];
    const float* Wx1    = (const float*)d_in[2];
    const float* Wh1    = (const float*)d_in[3];
    const float* b1     = (const float*)d_in[4];
    const float* Wx2    = (const float*)d_in[5];
    const float* Wh2    = (const float*)d_in[6];
    const float* b2     = (const float*)d_in[7];
    const float* Wd     = (const float*)d_in[8];
    const float* bd     = (const float*)d_in[9];
    float* out = (float*)d_out;

    build_xproj_kernel<<<VOCAB / 4, 256>>>(emb, Wx1, b1);

    cudaFuncSetAttribute(rnn_mma_kernel,
                         cudaFuncAttributeMaxDynamicSharedMemorySize, SMEM_NEED);
    rnn_mma_kernel<<<BATCH / MROWS, 256, SMEM_NEED>>>(
        tokens, Wh1, Wx2, Wh2, b2, Wd, bd, out);
}

// round 10
// speedup vs baseline: 1.1028x; 1.1028x over previous
#include <cuda_runtime.h>
#include <cuda_fp16.h>
#include <cstdint>

#define VOCAB 10000
#define EMBED 100
#define SEQ   80
#define UNITS 64
#define BATCH 16384
#define MROWS 128          // batch rows per CTA
#define XS    68           // xproj smem row stride (floats)
#define TKS   81           // token smem row stride (ints)

// xproj[v][u] = b1[u] + emb[v,:] @ Wx1[:,u]   (fp32, 2.56 MB, L2-resident)
__device__ float g_xproj[VOCAB * UNITS];

// ---------------------------------------------------------------------------
// helpers
// ---------------------------------------------------------------------------
__device__ __forceinline__ uint32_t smem_u32(const void* p) {
    uint32_t a;
    asm("{ .reg .u64 t; cvta.to.shared.u64 t, %1; cvt.u32.u64 %0, t; }" : "=r"(a) : "l"(p));
    return a;
}
#define SWZ(off) ((uint32_t)(off) ^ ((((uint32_t)(off)) >> 3) & 0x70))

// pack two f32 into f16x2 (lo -> low half, hi -> high half)
__device__ __forceinline__ uint32_t pack_f16(float lo, float hi) {
    uint32_t r; asm("cvt.rn.f16x2.f32 %0, %1, %2;" : "=r"(r) : "f"(hi), "f"(lo)); return r;
}
// dual tanh on packed f16x2 (1 MUFU op for 2 values)
__device__ __forceinline__ uint32_t tanh2(uint32_t x) {
    uint32_t r; asm("tanh.approx.f16x2 %0, %1;" : "=r"(r) : "r"(x)); return r;
}
__device__ __forceinline__ float2 unpk_f16(uint32_t u) {
    __half2 h = *reinterpret_cast<__half2*>(&u);
    return __half22float2(h);
}

// LDSM: volatile (pins ordering) but no memory clobber.
#define LDSM_X4(r0, r1, r2, r3, addr)                                       \
    asm volatile("ldmatrix.sync.aligned.m8n8.x4.shared.b16 {%0,%1,%2,%3}, [%4];" \
                 : "=r"(r0), "=r"(r1), "=r"(r2), "=r"(r3) : "r"(addr))

// MMA: NON-volatile pure register op — deps carried by operands; ptxas may
// interleave with MUFU/FADD/CVT streams.
#define MMA_F16(ac, A, b0, b1)                                              \
    asm("mma.sync.aligned.m16n8k16.row.col.f32.f16.f16.f32 "                \
        "{%0,%1,%2,%3}, {%4,%5,%6,%7}, {%8,%9}, {%0,%1,%2,%3};"             \
        : "+f"((ac)[0]), "+f"((ac)[1]), "+f"((ac)[2]), "+f"((ac)[3])        \
        : "r"((A)[0]), "r"((A)[1]), "r"((A)[2]), "r"((A)[3]),               \
          "r"(b0), "r"(b1))

#define CP_ASYNC_8(dst, src)                                                \
    asm volatile("cp.async.ca.shared.global [%0], [%1], 8;"                 \
                 :: "r"(dst), "l"(src) : "memory")
#define CP_COMMIT()  asm volatile("cp.async.commit_group;" ::: "memory")
#define CP_WAIT0()   asm volatile("cp.async.wait_group 0;" ::: "memory")

// ---------------------------------------------------------------------------
// Kernel A: build xproj table
// ---------------------------------------------------------------------------
__global__ void build_xproj_kernel(const float* __restrict__ emb,
                                   const float* __restrict__ Wx1,
                                   const float* __restrict__ b1) {
    __shared__ float se[4 * EMBED];
    const int v0  = blockIdx.x * 4;
    const int tid = threadIdx.x;
    for (int i = tid; i < 4 * EMBED; i += 256)
        se[i] = emb[v0 * EMBED + i];
    __syncthreads();
    const int vl = tid >> 6;
    const int u  = tid & 63;
    const float* er = se + vl * EMBED;
    float a0 = 0.f, a1 = 0.f;
#pragma unroll
    for (int e = 0; e < EMBED; e += 2) {
        a0 += er[e]     * Wx1[e * UNITS + u];
        a1 += er[e + 1] * Wx1[(e + 1) * UNITS + u];
    }
    g_xproj[(v0 + vl) * UNITS + u] = b1[u] + a0 + a1;
}

// ---------------------------------------------------------------------------
// smem layout (byte offsets from 1024-aligned base)
// ---------------------------------------------------------------------------
#define OFF_W1   0                                  // Wh1^T [n][k] f16 SW128, 8KB
#define OFF_XS0  8192                               // xproj buf 0: 128 x 68 fp32
#define OFF_XS1  (OFF_XS0 + MROWS * XS * 4)         // xproj buf 1
#define OFF_TOK  (OFF_XS1 + MROWS * XS * 4)         // 128 x 81 int
#define OFF_B2   (OFF_TOK + MROWS * TKS * 4)
#define OFF_WD   (OFF_B2 + 256)
#define SMEM_NEED (OFF_WD + 256 + 1024)

// ---------------------------------------------------------------------------
// Kernel B: 8 independent warps x 16 rows x full 64 cols, fp16 datapath.
// h1/h2 in registers (C-frag == A-frag identity). Zero barriers in loop.
// ---------------------------------------------------------------------------
__global__ void __launch_bounds__(256, 1)
rnn_mma_kernel(const int*   __restrict__ tokens,
               const float* __restrict__ Wh1,
               const float* __restrict__ Wx2,
               const float* __restrict__ Wh2,
               const float* __restrict__ b2,
               const float* __restrict__ Wd,
               const float* __restrict__ bd,
               float*       __restrict__ out) {
    extern __shared__ char dynsmem[];
    char* smem = (char*)(((uintptr_t)dynsmem + 1023) & ~(uintptr_t)1023);
    const uint32_t sb = smem_u32(smem);
    int*   stok = (int*)(smem + OFF_TOK);
    float* sB2  = (float*)(smem + OFF_B2);
    float* sWd  = (float*)(smem + OFF_WD);

    const int tid  = threadIdx.x;
    const int lane = tid & 31;
    const int wid  = tid >> 5;
    const int gid  = lane >> 2;
    const int tig  = lane & 3;
    const int wrow16 = wid * 16;
    const int m0   = blockIdx.x * MROWS;

    // ---- persistent B-fragments (full 64 cols, f16): [nt][kt][2] ----
    uint32_t BX2[8][4][2], BH2[8][4][2];
#pragma unroll
    for (int nt = 0; nt < 8; nt++)
#pragma unroll
        for (int kt = 0; kt < 4; kt++) {
            const int n = nt * 8 + gid;
            const int k = kt * 16 + tig * 2;
            BX2[nt][kt][0] = pack_f16(Wx2[k * 64 + n],       Wx2[(k + 1) * 64 + n]);
            BX2[nt][kt][1] = pack_f16(Wx2[(k + 8) * 64 + n], Wx2[(k + 9) * 64 + n]);
            BH2[nt][kt][0] = pack_f16(Wh2[k * 64 + n],       Wh2[(k + 1) * 64 + n]);
            BH2[nt][kt][1] = pack_f16(Wh2[(k + 8) * 64 + n], Wh2[(k + 9) * 64 + n]);
        }

    // ---- init smem: Wh1^T tile [n][k] f16 SW128, tokens, b2, Wd ----
    for (int i = tid; i < UNITS * UNITS; i += 256) {
        int n = i >> 6, k = i & 63;
        *(__half*)(smem + OFF_W1 + SWZ(n * 128 + k * 2)) =
            __float2half(Wh1[k * 64 + n]);
    }
    {
        const int* gtok = tokens + m0 * SEQ;
        for (int i = tid; i < MROWS * SEQ; i += 256)
            stok[(i / SEQ) * TKS + (i % SEQ)] = gtok[i];
    }
    if (tid < UNITS) { sB2[tid] = b2[tid]; sWd[tid] = Wd[tid]; }
    __syncthreads();

    const uint32_t w1Base = sb + OFF_W1;
    const uint32_t bRow = (uint32_t)((((lane >> 4) << 3) | (lane & 7)));
    const uint32_t bKo  = (uint32_t)(((lane >> 3) & 1) << 3);
    const uint32_t xsLaneOff = (uint32_t)(wrow16 * XS * 4) + (uint32_t)(lane * 8);

    // h fragments (A-frag layout, f16x2), h0 = 0
    uint32_t h1f[4][4], h2f[4][4];
#pragma unroll
    for (int kt = 0; kt < 4; kt++)
#pragma unroll
        for (int j = 0; j < 4; j++) { h1f[kt][j] = 0u; h2f[kt][j] = 0u; }

    float acc1[8][4], acc2[8][4];

    for (int t = 0; t < SEQ; t++) {
        float* xs = (float*)(smem + ((t & 1) ? OFF_XS1 : OFF_XS0));
        const uint32_t xsDst = sb + ((t & 1) ? OFF_XS1 : OFF_XS0) + xsLaneOff;

        // ---- coalesced async xproj gather for this warp's 16 rows ----
        {
            int tokreg = 0;
            if (lane < 16) tokreg = stok[(wrow16 + lane) * TKS + t];
#pragma unroll
            for (int r = 0; r < 16; r++) {
                const int tok = __shfl_sync(0xffffffffu, tokreg, r);
                CP_ASYNC_8(xsDst + (uint32_t)(r * XS * 4), g_xproj + tok * UNITS + lane * 2);
            }
            CP_COMMIT();
        }

        // ---- gemm1 (h1 @ Wh1, streamed B) interleaved with gemm2a (h2 @ Wh2) ----
#pragma unroll
        for (int nt = 0; nt < 8; nt++)
#pragma unroll
            for (int c = 0; c < 4; c++) { acc1[nt][c] = 0.f; acc2[nt][c] = 0.f; }
#pragma unroll
        for (int kt = 0; kt < 4; kt++) {
            uint32_t Bs[4][4];
#pragma unroll
            for (int np = 0; np < 4; np++)
                LDSM_X4(Bs[np][0], Bs[np][1], Bs[np][2], Bs[np][3],
                        w1Base + SWZ((np * 16 + bRow) * 128 + (kt * 16 + bKo) * 2));
#pragma unroll
            for (int nt = 0; nt < 8; nt++)
                MMA_F16(acc2[nt], h2f[kt], BH2[nt][kt][0], BH2[nt][kt][1]);
#pragma unroll
            for (int np = 0; np < 4; np++) {
                MMA_F16(acc1[2 * np],     h1f[kt], Bs[np][0], Bs[np][1]);
                MMA_F16(acc1[2 * np + 1], h1f[kt], Bs[np][2], Bs[np][3]);
            }
        }

        CP_WAIT0();   // own warp's xproj rows landed — no barrier needed

        // ---- epi1: h1 = tanh(acc1 + xproj); pack IS the tanh input ----
        {
            const int r0 = wrow16 + gid;
#pragma unroll
            for (int nt = 0; nt < 8; nt++) {
                const int col = nt * 8 + tig * 2;
                float2 xa = *(const float2*)(xs + r0 * XS + col);
                float2 xb = *(const float2*)(xs + (r0 + 8) * XS + col);
                h1f[nt >> 1][(nt & 1) * 2 + 0] =
                    tanh2(pack_f16(acc1[nt][0] + xa.x, acc1[nt][1] + xa.y));
                h1f[nt >> 1][(nt & 1) * 2 + 1] =
                    tanh2(pack_f16(acc1[nt][2] + xb.x, acc1[nt][3] + xb.y));
            }
        }

        // ---- gemm2b: acc2 += h1_new @ Wx2 (all registers) ----
#pragma unroll
        for (int kt = 0; kt < 4; kt++)
#pragma unroll
            for (int nt = 0; nt < 8; nt++)
                MMA_F16(acc2[nt], h1f[kt], BX2[nt][kt][0], BX2[nt][kt][1]);

        // ---- epi2: h2 = tanh(acc2 + b2) -> A-frags ----
#pragma unroll
        for (int nt = 0; nt < 8; nt++) {
            const int col = nt * 8 + tig * 2;
            float2 bb = *(const float2*)(sB2 + col);
            h2f[nt >> 1][(nt & 1) * 2 + 0] =
                tanh2(pack_f16(acc2[nt][0] + bb.x, acc2[nt][1] + bb.y));
            h2f[nt >> 1][(nt & 1) * 2 + 1] =
                tanh2(pack_f16(acc2[nt][2] + bb.x, acc2[nt][3] + bb.y));
        }
    }

    // ---- head: out = sigmoid(h2 . Wd + bd); reduce over tig group ----
    float z0 = 0.f, z1 = 0.f;
#pragma unroll
    for (int nt = 0; nt < 8; nt++) {
        const int col = nt * 8 + tig * 2;
        float2 wd = *(const float2*)(sWd + col);
        float2 a = unpk_f16(h2f[nt >> 1][(nt & 1) * 2 + 0]);   // row gid
        float2 b = unpk_f16(h2f[nt >> 1][(nt & 1) * 2 + 1]);   // row gid+8
        z0 += a.x * wd.x + a.y * wd.y;
        z1 += b.x * wd.x + b.y * wd.y;
    }
    z0 += __shfl_xor_sync(0xffffffffu, z0, 1);
    z0 += __shfl_xor_sync(0xffffffffu, z0, 2);
    z1 += __shfl_xor_sync(0xffffffffu, z1, 1);
    z1 += __shfl_xor_sync(0xffffffffu, z1, 2);
    if (tig == 0) {
        const float bd0 = bd[0];
        out[m0 + wrow16 + gid]     = 1.0f / (1.0f + __expf(-(z0 + bd0)));
        out[m0 + wrow16 + gid + 8] = 1.0f / (1.0f + __expf(-(z1 + bd0)));
    }
}

// ---------------------------------------------------------------------------
extern "C" void kernel_launch(void* const* d_in, const int* in_sizes, int n_in,
                              void* d_out, int out_size) {
    const int*   tokens = (const int*)  d_in[0];
    const float* emb    = (const float*)d_in[1];
    const float* Wx1    = (const float*)d_in[2];
    const float* Wh1    = (const float*)d_in[3];
    const float* b1     = (const float*)d_in[4];
    const float* Wx2    = (const float*)d_in[5];
    const float* Wh2    = (const float*)d_in[6];
    const float* b2     = (const float*)d_in[7];
    const float* Wd     = (const float*)d_in[8];
    const float* bd     = (const float*)d_in[9];
    float* out = (float*)d_out;

    build_xproj_kernel<<<VOCAB / 4, 256>>>(emb, Wx1, b1);

    cudaFuncSetAttribute(rnn_mma_kernel,
                         cudaFuncAttributeMaxDynamicSharedMemorySize, SMEM_NEED);
    rnn_mma_kernel<<<BATCH / MROWS, 256, SMEM_NEED>>>(
        tokens, Wh1, Wx2, Wh2, b2, Wd, bd, out);
}

// round 11
// speedup vs baseline: 1.1749x; 1.0654x over previous
#include <cuda_runtime.h>
#include <cuda_fp16.h>
#include <cstdint>

#define VOCAB 10000
#define EMBED 100
#define SEQ   80
#define UNITS 64
#define BATCH 16384
#define MROWS 128          // batch rows per CTA
#define XS    68           // xproj smem row stride (floats)
#define TKS   81           // token smem row stride (ints)

// xproj[v][u] = b1[u] + emb[v,:] @ Wx1[:,u]   (fp32, 2.56 MB, L2-resident)
__device__ float g_xproj[VOCAB * UNITS];

// ---------------------------------------------------------------------------
// helpers
// ---------------------------------------------------------------------------
__device__ __forceinline__ uint32_t smem_u32(const void* p) {
    uint32_t a;
    asm("{ .reg .u64 t; cvta.to.shared.u64 t, %1; cvt.u32.u64 %0, t; }" : "=r"(a) : "l"(p));
    return a;
}
#define SWZ(off) ((uint32_t)(off) ^ ((((uint32_t)(off)) >> 3) & 0x70))

// pack two f32 into f16x2 (lo -> low half, hi -> high half)
__device__ __forceinline__ uint32_t pack_f16(float lo, float hi) {
    uint32_t r; asm("cvt.rn.f16x2.f32 %0, %1, %2;" : "=r"(r) : "f"(hi), "f"(lo)); return r;
}
// dual tanh on packed f16x2
__device__ __forceinline__ uint32_t tanh2(uint32_t x) {
    uint32_t r; asm("tanh.approx.f16x2 %0, %1;" : "=r"(r) : "r"(x)); return r;
}
__device__ __forceinline__ float2 unpk_f16(uint32_t u) {
    __half2 h = *reinterpret_cast<__half2*>(&u);
    return __half22float2(h);
}

// LDSM: volatile (pins ordering) but no memory clobber.
#define LDSM_X4(r0, r1, r2, r3, addr)                                       \
    asm volatile("ldmatrix.sync.aligned.m8n8.x4.shared.b16 {%0,%1,%2,%3}, [%4];" \
                 : "=r"(r0), "=r"(r1), "=r"(r2), "=r"(r3) : "r"(addr))

// MMA: NON-volatile pure register op — deps carried by operands.
#define MMA_F16(ac, A, b0, b1)                                              \
    asm("mma.sync.aligned.m16n8k16.row.col.f32.f16.f16.f32 "                \
        "{%0,%1,%2,%3}, {%4,%5,%6,%7}, {%8,%9}, {%0,%1,%2,%3};"             \
        : "+f"((ac)[0]), "+f"((ac)[1]), "+f"((ac)[2]), "+f"((ac)[3])        \
        : "r"((A)[0]), "r"((A)[1]), "r"((A)[2]), "r"((A)[3]),               \
          "r"(b0), "r"(b1))

#define CP_ASYNC_8(dst, src)                                                \
    asm volatile("cp.async.ca.shared.global [%0], [%1], 8;"                 \
                 :: "r"(dst), "l"(src) : "memory")
#define CP_COMMIT()  asm volatile("cp.async.commit_group;" ::: "memory")
#define CP_WAIT1()   asm volatile("cp.async.wait_group 1;" ::: "memory")
#define CP_WAIT0()   asm volatile("cp.async.wait_group 0;" ::: "memory")

// ---------------------------------------------------------------------------
// Kernel A: build xproj table
// ---------------------------------------------------------------------------
__global__ void build_xproj_kernel(const float* __restrict__ emb,
                                   const float* __restrict__ Wx1,
                                   const float* __restrict__ b1) {
    __shared__ float se[4 * EMBED];
    const int v0  = blockIdx.x * 4;
    const int tid = threadIdx.x;
    for (int i = tid; i < 4 * EMBED; i += 256)
        se[i] = emb[v0 * EMBED + i];
    __syncthreads();
    const int vl = tid >> 6;
    const int u  = tid & 63;
    const float* er = se + vl * EMBED;
    float a0 = 0.f, a1 = 0.f;
#pragma unroll
    for (int e = 0; e < EMBED; e += 2) {
        a0 += er[e]     * Wx1[e * UNITS + u];
        a1 += er[e + 1] * Wx1[(e + 1) * UNITS + u];
    }
    g_xproj[(v0 + vl) * UNITS + u] = b1[u] + a0 + a1;
}

// ---------------------------------------------------------------------------
// smem layout (byte offsets from 1024-aligned base)
// ---------------------------------------------------------------------------
#define OFF_W1   0                                  // Wh1^T [n][k] f16 SW128, 8KB
#define OFF_XS0  8192                               // xproj buf 0: 128 x 68 fp32
#define OFF_XS1  (OFF_XS0 + MROWS * XS * 4)         // xproj buf 1
#define OFF_TOK  (OFF_XS1 + MROWS * XS * 4)         // 128 x 81 int
#define OFF_B2   (OFF_TOK + MROWS * TKS * 4)
#define OFF_WD   (OFF_B2 + 256)
#define SMEM_NEED (OFF_WD + 256 + 1024)

// ---------------------------------------------------------------------------
// Kernel B: 8 independent warps x 16 rows x full 64 cols, fp16 datapath.
// acc1 starts at xproj (prefetched), acc2 starts at b2 — epilogues are
// pack+tanh only; no zero-init MOVs, no epilogue FADDs.
// ---------------------------------------------------------------------------
__global__ void __launch_bounds__(256, 1)
rnn_mma_kernel(const int*   __restrict__ tokens,
               const float* __restrict__ Wh1,
               const float* __restrict__ Wx2,
               const float* __restrict__ Wh2,
               const float* __restrict__ b2,
               const float* __restrict__ Wd,
               const float* __restrict__ bd,
               float*       __restrict__ out) {
    extern __shared__ char dynsmem[];
    char* smem = (char*)(((uintptr_t)dynsmem + 1023) & ~(uintptr_t)1023);
    const uint32_t sb = smem_u32(smem);
    int*   stok = (int*)(smem + OFF_TOK);
    float* sB2  = (float*)(smem + OFF_B2);
    float* sWd  = (float*)(smem + OFF_WD);

    const int tid  = threadIdx.x;
    const int lane = tid & 31;
    const int wid  = tid >> 5;
    const int gid  = lane >> 2;
    const int tig  = lane & 3;
    const int wrow16 = wid * 16;
    const int m0   = blockIdx.x * MROWS;

    // ---- persistent B-fragments (full 64 cols, f16): [nt][kt][2] ----
    uint32_t BX2[8][4][2], BH2[8][4][2];
#pragma unroll
    for (int nt = 0; nt < 8; nt++)
#pragma unroll
        for (int kt = 0; kt < 4; kt++) {
            const int n = nt * 8 + gid;
            const int k = kt * 16 + tig * 2;
            BX2[nt][kt][0] = pack_f16(Wx2[k * 64 + n],       Wx2[(k + 1) * 64 + n]);
            BX2[nt][kt][1] = pack_f16(Wx2[(k + 8) * 64 + n], Wx2[(k + 9) * 64 + n]);
            BH2[nt][kt][0] = pack_f16(Wh2[k * 64 + n],       Wh2[(k + 1) * 64 + n]);
            BH2[nt][kt][1] = pack_f16(Wh2[(k + 8) * 64 + n], Wh2[(k + 9) * 64 + n]);
        }

    // ---- init smem: Wh1^T tile [n][k] f16 SW128, tokens, b2, Wd ----
    for (int i = tid; i < UNITS * UNITS; i += 256) {
        int n = i >> 6, k = i & 63;
        *(__half*)(smem + OFF_W1 + SWZ(n * 128 + k * 2)) =
            __float2half(Wh1[k * 64 + n]);
    }
    {
        const int* gtok = tokens + m0 * SEQ;
        for (int i = tid; i < MROWS * SEQ; i += 256)
            stok[(i / SEQ) * TKS + (i % SEQ)] = gtok[i];
    }
    if (tid < UNITS) { sB2[tid] = b2[tid]; sWd[tid] = Wd[tid]; }
    __syncthreads();

    const uint32_t w1Base = sb + OFF_W1;
    const uint32_t bRow = (uint32_t)((((lane >> 4) << 3) | (lane & 7)));
    const uint32_t bKo  = (uint32_t)(((lane >> 3) & 1) << 3);
    const uint32_t xsLaneOff = (uint32_t)(wrow16 * XS * 4) + (uint32_t)(lane * 8);

    // h fragments (A-frag layout, f16x2), h0 = 0
    uint32_t h1f[4][4], h2f[4][4];
#pragma unroll
    for (int kt = 0; kt < 4; kt++)
#pragma unroll
        for (int j = 0; j < 4; j++) { h1f[kt][j] = 0u; h2f[kt][j] = 0u; }

    float acc1[8][4], acc2[8][4];

    // ---- prime the gather pipeline: step 0 into buf 0 ----
    {
        int tokreg = 0;
        if (lane < 16) tokreg = stok[(wrow16 + lane) * TKS + 0];
        const uint32_t dst = sb + OFF_XS0 + xsLaneOff;
#pragma unroll
        for (int r = 0; r < 16; r++) {
            const int tok = __shfl_sync(0xffffffffu, tokreg, r);
            CP_ASYNC_8(dst + (uint32_t)(r * XS * 4), g_xproj + tok * UNITS + lane * 2);
        }
        CP_COMMIT();
    }

    for (int t = 0; t < SEQ; t++) {
        float* xs = (float*)(smem + ((t & 1) ? OFF_XS1 : OFF_XS0));

        // ---- prefetch gather for t+1; then wait for step t's rows ----
        if (t + 1 < SEQ) {
            int tokreg = 0;
            if (lane < 16) tokreg = stok[(wrow16 + lane) * TKS + (t + 1)];
            const uint32_t dst = sb + (((t + 1) & 1) ? OFF_XS1 : OFF_XS0) + xsLaneOff;
#pragma unroll
            for (int r = 0; r < 16; r++) {
                const int tok = __shfl_sync(0xffffffffu, tokreg, r);
                CP_ASYNC_8(dst + (uint32_t)(r * XS * 4), g_xproj + tok * UNITS + lane * 2);
            }
            CP_COMMIT();
            CP_WAIT1();
        } else {
            CP_WAIT0();
        }

        // ---- init: acc1 = xproj(t) (fused bias+input), acc2 = b2 ----
        {
            const int r0 = wrow16 + gid;
#pragma unroll
            for (int nt = 0; nt < 8; nt++) {
                const int col = nt * 8 + tig * 2;
                float2 xa = *(const float2*)(xs + r0 * XS + col);
                float2 xb = *(const float2*)(xs + (r0 + 8) * XS + col);
                acc1[nt][0] = xa.x; acc1[nt][1] = xa.y;
                acc1[nt][2] = xb.x; acc1[nt][3] = xb.y;
                float2 bb = *(const float2*)(sB2 + col);
                acc2[nt][0] = bb.x; acc2[nt][1] = bb.y;
                acc2[nt][2] = bb.x; acc2[nt][3] = bb.y;
            }
        }

        // ---- gemm1 (h1 @ Wh1, streamed B) interleaved with gemm2a (h2 @ Wh2) ----
#pragma unroll
        for (int kt = 0; kt < 4; kt++) {
            uint32_t Bs[4][4];
#pragma unroll
            for (int np = 0; np < 4; np++)
                LDSM_X4(Bs[np][0], Bs[np][1], Bs[np][2], Bs[np][3],
                        w1Base + SWZ((np * 16 + bRow) * 128 + (kt * 16 + bKo) * 2));
#pragma unroll
            for (int nt = 0; nt < 8; nt++)
                MMA_F16(acc2[nt], h2f[kt], BH2[nt][kt][0], BH2[nt][kt][1]);
#pragma unroll
            for (int np = 0; np < 4; np++) {
                MMA_F16(acc1[2 * np],     h1f[kt], Bs[np][0], Bs[np][1]);
                MMA_F16(acc1[2 * np + 1], h1f[kt], Bs[np][2], Bs[np][3]);
            }
        }

        // ---- epi1: h1 = tanh(acc1) — pack IS the tanh input, no adds ----
#pragma unroll
        for (int nt = 0; nt < 8; nt++) {
            h1f[nt >> 1][(nt & 1) * 2 + 0] = tanh2(pack_f16(acc1[nt][0], acc1[nt][1]));
            h1f[nt >> 1][(nt & 1) * 2 + 1] = tanh2(pack_f16(acc1[nt][2], acc1[nt][3]));
        }

        // ---- gemm2b: acc2 += h1_new @ Wx2 (all registers) ----
#pragma unroll
        for (int kt = 0; kt < 4; kt++)
#pragma unroll
            for (int nt = 0; nt < 8; nt++)
                MMA_F16(acc2[nt], h1f[kt], BX2[nt][kt][0], BX2[nt][kt][1]);

        // ---- epi2: h2 = tanh(acc2) — no adds ----
#pragma unroll
        for (int nt = 0; nt < 8; nt++) {
            h2f[nt >> 1][(nt & 1) * 2 + 0] = tanh2(pack_f16(acc2[nt][0], acc2[nt][1]));
            h2f[nt >> 1][(nt & 1) * 2 + 1] = tanh2(pack_f16(acc2[nt][2], acc2[nt][3]));
        }
    }

    // ---- head: out = sigmoid(h2 . Wd + bd); reduce over tig group ----
    float z0 = 0.f, z1 = 0.f;
#pragma unroll
    for (int nt = 0; nt < 8; nt++) {
        const int col = nt * 8 + tig * 2;
        float2 wd = *(const float2*)(sWd + col);
        float2 a = unpk_f16(h2f[nt >> 1][(nt & 1) * 2 + 0]);   // row gid
        float2 b = unpk_f16(h2f[nt >> 1][(nt & 1) * 2 + 1]);   // row gid+8
        z0 += a.x * wd.x + a.y * wd.y;
        z1 += b.x * wd.x + b.y * wd.y;
    }
    z0 += __shfl_xor_sync(0xffffffffu, z0, 1);
    z0 += __shfl_xor_sync(0xffffffffu, z0, 2);
    z1 += __shfl_xor_sync(0xffffffffu, z1, 1);
    z1 += __shfl_xor_sync(0xffffffffu, z1, 2);
    if (tig == 0) {
        const float bd0 = bd[0];
        out[m0 + wrow16 + gid]     = 1.0f / (1.0f + __expf(-(z0 + bd0)));
        out[m0 + wrow16 + gid + 8] = 1.0f / (1.0f + __expf(-(z1 + bd0)));
    }
}

// ---------------------------------------------------------------------------
extern "C" void kernel_launch(void* const* d_in, const int* in_sizes, int n_in,
                              void* d_out, int out_size) {
    const int*   tokens = (const int*)  d_in[0];
    const float* emb    = (const float*)d_in[1];
    const float* Wx1    = (const float*)d_in[2];
    const float* Wh1    = (const float*)d_in[3];
    const float* b1     = (const float*)d_in[4];
    const float* Wx2    = (const float*)d_in[5];
    const float* Wh2    = (const float*)d_in[6];
    const float* b2     = (const float*)d_in[7];
    const float* Wd     = (const float*)d_in[8];
    const float* bd     = (const float*)d_in[9];
    float* out = (float*)d_out;

    build_xproj_kernel<<<VOCAB / 4, 256>>>(emb, Wx1, b1);

    cudaFuncSetAttribute(rnn_mma_kernel,
                         cudaFuncAttributeMaxDynamicSharedMemorySize, SMEM_NEED);
    rnn_mma_kernel<<<BATCH / MROWS, 256, SMEM_NEED>>>(
        tokens, Wh1, Wx2, Wh2, b2, Wd, bd, out);
}

// round 12
// speedup vs baseline: 1.2493x; 1.0633x over previous
#include <cuda_runtime.h>
#include <cuda_fp16.h>
#include <cstdint>

#define VOCAB 10000
#define EMBED 100
#define SEQ   80
#define UNITS 64
#define BATCH 16384
#define MROWS 128          // batch rows per CTA
#define XSB   144          // xs row stride BYTES (128B data + 16B pad; ≡4 words mod 32 → conflict-free init)
#define TKS   81           // token smem row stride (ints)

// xproj[v][u] = b1[u] + emb[v,:] @ Wx1[:,u]   (f16, 1.28 MB, L2-resident)
__device__ __half g_xproj_h[VOCAB * UNITS];

// ---------------------------------------------------------------------------
// helpers
// ---------------------------------------------------------------------------
__device__ __forceinline__ uint32_t smem_u32(const void* p) {
    uint32_t a;
    asm("{ .reg .u64 t; cvta.to.shared.u64 t, %1; cvt.u32.u64 %0, t; }" : "=r"(a) : "l"(p));
    return a;
}
#define SWZ(off) ((uint32_t)(off) ^ ((((uint32_t)(off)) >> 3) & 0x70))

__device__ __forceinline__ uint32_t pack_f16(float lo, float hi) {
    uint32_t r; asm("cvt.rn.f16x2.f32 %0, %1, %2;" : "=r"(r) : "f"(hi), "f"(lo)); return r;
}
__device__ __forceinline__ uint32_t tanh2(uint32_t x) {
    uint32_t r; asm("tanh.approx.f16x2 %0, %1;" : "=r"(r) : "r"(x)); return r;
}
__device__ __forceinline__ float2 unpk_f16(uint32_t u) {
    __half2 h = *reinterpret_cast<__half2*>(&u);
    return __half22float2(h);
}

// LDSM: volatile (pins ordering) but no memory clobber.
#define LDSM_X4(r0, r1, r2, r3, addr)                                       \
    asm volatile("ldmatrix.sync.aligned.m8n8.x4.shared.b16 {%0,%1,%2,%3}, [%4];" \
                 : "=r"(r0), "=r"(r1), "=r"(r2), "=r"(r3) : "r"(addr))

// MMA with f16 C/D: D-frag (2 regs, f16x2) == half of an A-frag. Non-volatile.
#define MMA_F16C(ac, A, b0, b1)                                             \
    asm("mma.sync.aligned.m16n8k16.row.col.f16.f16.f16.f16 "                \
        "{%0,%1}, {%2,%3,%4,%5}, {%6,%7}, {%0,%1};"                         \
        : "+r"((ac)[0]), "+r"((ac)[1])                                      \
        : "r"((A)[0]), "r"((A)[1]), "r"((A)[2]), "r"((A)[3]),               \
          "r"(b0), "r"(b1))

#define CP_ASYNC_4(dst, src)                                                \
    asm volatile("cp.async.ca.shared.global [%0], [%1], 4;"                 \
                 :: "r"(dst), "l"(src) : "memory")
#define CP_COMMIT()  asm volatile("cp.async.commit_group;" ::: "memory")
#define CP_WAIT1()   asm volatile("cp.async.wait_group 1;" ::: "memory")
#define CP_WAIT0()   asm volatile("cp.async.wait_group 0;" ::: "memory")

// ---------------------------------------------------------------------------
// Kernel A: build xproj table (f16 output)
// ---------------------------------------------------------------------------
__global__ void build_xproj_kernel(const float* __restrict__ emb,
                                   const float* __restrict__ Wx1,
                                   const float* __restrict__ b1) {
    __shared__ float se[4 * EMBED];
    const int v0  = blockIdx.x * 4;
    const int tid = threadIdx.x;
    for (int i = tid; i < 4 * EMBED; i += 256)
        se[i] = emb[v0 * EMBED + i];
    __syncthreads();
    const int vl = tid >> 6;
    const int u  = tid & 63;
    const float* er = se + vl * EMBED;
    float a0 = 0.f, a1 = 0.f;
#pragma unroll
    for (int e = 0; e < EMBED; e += 2) {
        a0 += er[e]     * Wx1[e * UNITS + u];
        a1 += er[e + 1] * Wx1[(e + 1) * UNITS + u];
    }
    g_xproj_h[(v0 + vl) * UNITS + u] = __float2half(b1[u] + a0 + a1);
}

// ---------------------------------------------------------------------------
// smem layout (byte offsets from 1024-aligned base)
// ---------------------------------------------------------------------------
#define OFF_W1   0                                  // Wh1^T [n][k] f16 SW128, 8KB
#define OFF_XS0  8192                               // xs buf 0: 128 rows x 144B (f16)
#define OFF_XS1  (OFF_XS0 + MROWS * XSB)
#define OFF_TOK  (OFF_XS1 + MROWS * XSB)            // 128 x 81 int
#define OFF_WD   (OFF_TOK + MROWS * TKS * 4)
#define SMEM_NEED (OFF_WD + 256 + 1024)

// ---------------------------------------------------------------------------
// Kernel B: 8 independent warps x 16 rows x 64 cols, full-f16 datapath.
// f16 accumulators: epilogue = tanh2 on the acc regs; zero CVT, zero FADD.
// ---------------------------------------------------------------------------
__global__ void __launch_bounds__(256, 1)
rnn_mma_kernel(const int*   __restrict__ tokens,
               const float* __restrict__ Wh1,
               const float* __restrict__ Wx2,
               const float* __restrict__ Wh2,
               const float* __restrict__ b2,
               const float* __restrict__ Wd,
               const float* __restrict__ bd,
               float*       __restrict__ out) {
    extern __shared__ char dynsmem[];
    char* smem = (char*)(((uintptr_t)dynsmem + 1023) & ~(uintptr_t)1023);
    const uint32_t sb = smem_u32(smem);
    int*   stok = (int*)(smem + OFF_TOK);
    float* sWd  = (float*)(smem + OFF_WD);

    const int tid  = threadIdx.x;
    const int lane = tid & 31;
    const int wid  = tid >> 5;
    const int gid  = lane >> 2;
    const int tig  = lane & 3;
    const int wrow16 = wid * 16;
    const int m0   = blockIdx.x * MROWS;

    // ---- persistent B-fragments (full 64 cols, f16): [nt][kt][2] ----
    uint32_t BX2[8][4][2], BH2[8][4][2];
#pragma unroll
    for (int nt = 0; nt < 8; nt++)
#pragma unroll
        for (int kt = 0; kt < 4; kt++) {
            const int n = nt * 8 + gid;
            const int k = kt * 16 + tig * 2;
            BX2[nt][kt][0] = pack_f16(Wx2[k * 64 + n],       Wx2[(k + 1) * 64 + n]);
            BX2[nt][kt][1] = pack_f16(Wx2[(k + 8) * 64 + n], Wx2[(k + 9) * 64 + n]);
            BH2[nt][kt][0] = pack_f16(Wh2[k * 64 + n],       Wh2[(k + 1) * 64 + n]);
            BH2[nt][kt][1] = pack_f16(Wh2[(k + 8) * 64 + n], Wh2[(k + 9) * 64 + n]);
        }
    // persistent b2 f16x2 (same pair for row g and g+8)
    uint32_t b2v[8];
#pragma unroll
    for (int nt = 0; nt < 8; nt++)
        b2v[nt] = pack_f16(b2[nt * 8 + tig * 2], b2[nt * 8 + tig * 2 + 1]);

    // ---- init smem: Wh1^T tile [n][k] f16 SW128, tokens, Wd ----
    for (int i = tid; i < UNITS * UNITS; i += 256) {
        int n = i >> 6, k = i & 63;
        *(__half*)(smem + OFF_W1 + SWZ(n * 128 + k * 2)) =
            __float2half(Wh1[k * 64 + n]);
    }
    {
        const int* gtok = tokens + m0 * SEQ;
        for (int i = tid; i < MROWS * SEQ; i += 256)
            stok[(i / SEQ) * TKS + (i % SEQ)] = gtok[i];
    }
    if (tid < UNITS) sWd[tid] = Wd[tid];
    __syncthreads();

    const uint32_t w1Base = sb + OFF_W1;
    const uint32_t bRow = (uint32_t)((((lane >> 4) << 3) | (lane & 7)));
    const uint32_t bKo  = (uint32_t)(((lane >> 3) & 1) << 3);
    const uint32_t xsLaneOff = (uint32_t)(wrow16 * XSB) + (uint32_t)(lane * 4);

    // h fragments (A-frag layout, f16x2), h0 = 0
    uint32_t h1f[4][4], h2f[4][4];
#pragma unroll
    for (int kt = 0; kt < 4; kt++)
#pragma unroll
        for (int j = 0; j < 4; j++) { h1f[kt][j] = 0u; h2f[kt][j] = 0u; }

    uint32_t acc1[8][2], acc2[8][2];   // f16x2 accumulators

    // ---- prime gather pipeline: step 0 into buf 0 (4B/lane, 1 row/instr) ----
    {
        int tokreg = 0;
        if (lane < 16) tokreg = stok[(wrow16 + lane) * TKS + 0];
        const uint32_t dst = sb + OFF_XS0 + xsLaneOff;
#pragma unroll
        for (int r = 0; r < 16; r++) {
            const int tok = __shfl_sync(0xffffffffu, tokreg, r);
            CP_ASYNC_4(dst + (uint32_t)(r * XSB), g_xproj_h + tok * UNITS + lane * 2);
        }
        CP_COMMIT();
    }

    for (int t = 0; t < SEQ; t++) {
        const uint32_t xsOff = (t & 1) ? OFF_XS1 : OFF_XS0;

        // ---- prefetch gather for t+1; wait for step t's rows ----
        if (t + 1 < SEQ) {
            int tokreg = 0;
            if (lane < 16) tokreg = stok[(wrow16 + lane) * TKS + (t + 1)];
            const uint32_t dst = sb + (((t + 1) & 1) ? OFF_XS1 : OFF_XS0) + xsLaneOff;
#pragma unroll
            for (int r = 0; r < 16; r++) {
                const int tok = __shfl_sync(0xffffffffu, tokreg, r);
                CP_ASYNC_4(dst + (uint32_t)(r * XSB), g_xproj_h + tok * UNITS + lane * 2);
            }
            CP_COMMIT();
            CP_WAIT1();
        } else {
            CP_WAIT0();
        }

        // ---- init: acc1 = xproj(t) (f16x2 LDS, bank-conflict-free), acc2 = b2 ----
        {
            const uint32_t base = (uint32_t)(uintptr_t)(smem + xsOff)
                                - (uint32_t)(uintptr_t)smem;   // = xsOff
            const char* xrow0 = smem + xsOff + (wrow16 + gid) * XSB + tig * 4;
#pragma unroll
            for (int nt = 0; nt < 8; nt++) {
                acc1[nt][0] = *(const uint32_t*)(xrow0 + nt * 16);
                acc1[nt][1] = *(const uint32_t*)(xrow0 + 8 * XSB + nt * 16);
                acc2[nt][0] = b2v[nt];
                acc2[nt][1] = b2v[nt];
            }
            (void)base;
        }

        // ---- gemm1 (h1 @ Wh1, streamed B) interleaved with gemm2a (h2 @ Wh2) ----
#pragma unroll
        for (int kt = 0; kt < 4; kt++) {
            uint32_t Bs[4][4];
#pragma unroll
            for (int np = 0; np < 4; np++)
                LDSM_X4(Bs[np][0], Bs[np][1], Bs[np][2], Bs[np][3],
                        w1Base + SWZ((np * 16 + bRow) * 128 + (kt * 16 + bKo) * 2));
#pragma unroll
            for (int nt = 0; nt < 8; nt++)
                MMA_F16C(acc2[nt], h2f[kt], BH2[nt][kt][0], BH2[nt][kt][1]);
#pragma unroll
            for (int np = 0; np < 4; np++) {
                MMA_F16C(acc1[2 * np],     h1f[kt], Bs[np][0], Bs[np][1]);
                MMA_F16C(acc1[2 * np + 1], h1f[kt], Bs[np][2], Bs[np][3]);
            }
        }

        // ---- epi1: h1 = tanh2(acc1) — accumulator IS the next A-frag ----
#pragma unroll
        for (int nt = 0; nt < 8; nt++) {
            h1f[nt >> 1][(nt & 1) * 2 + 0] = tanh2(acc1[nt][0]);
            h1f[nt >> 1][(nt & 1) * 2 + 1] = tanh2(acc1[nt][1]);
        }

        // ---- gemm2b: acc2 += h1_new @ Wx2 (all registers) ----
#pragma unroll
        for (int kt = 0; kt < 4; kt++)
#pragma unroll
            for (int nt = 0; nt < 8; nt++)
                MMA_F16C(acc2[nt], h1f[kt], BX2[nt][kt][0], BX2[nt][kt][1]);

        // ---- epi2: h2 = tanh2(acc2) ----
#pragma unroll
        for (int nt = 0; nt < 8; nt++) {
            h2f[nt >> 1][(nt & 1) * 2 + 0] = tanh2(acc2[nt][0]);
            h2f[nt >> 1][(nt & 1) * 2 + 1] = tanh2(acc2[nt][1]);
        }
    }

    // ---- head: out = sigmoid(h2 . Wd + bd); reduce over tig group ----
    float z0 = 0.f, z1 = 0.f;
#pragma unroll
    for (int nt = 0; nt < 8; nt++) {
        const int col = nt * 8 + tig * 2;
        float2 wd = *(const float2*)(sWd + col);
        float2 a = unpk_f16(h2f[nt >> 1][(nt & 1) * 2 + 0]);   // row gid
        float2 b = unpk_f16(h2f[nt >> 1][(nt & 1) * 2 + 1]);   // row gid+8
        z0 += a.x * wd.x + a.y * wd.y;
        z1 += b.x * wd.x + b.y * wd.y;
    }
    z0 += __shfl_xor_sync(0xffffffffu, z0, 1);
    z0 += __shfl_xor_sync(0xffffffffu, z0, 2);
    z1 += __shfl_xor_sync(0xffffffffu, z1, 1);
    z1 += __shfl_xor_sync(0xffffffffu, z1, 2);
    if (tig == 0) {
        const float bd0 = bd[0];
        out[m0 + wrow16 + gid]     = 1.0f / (1.0f + __expf(-(z0 + bd0)));
        out[m0 + wrow16 + gid + 8] = 1.0f / (1.0f + __expf(-(z1 + bd0)));
    }
}

// ---------------------------------------------------------------------------
extern "C" void kernel_launch(void* const* d_in, const int* in_sizes, int n_in,
                              void* d_out, int out_size) {
    const int*   tokens = (const int*)  d_in[0];
    const float* emb    = (const float*)d_in[1];
    const float* Wx1    = (const float*)d_in[2];
    const float* Wh1    = (const float*)d_in[3];
    const float* b1     = (const float*)d_in[4];
    const float* Wx2    = (const float*)d_in[5];
    const float* Wh2    = (const float*)d_in[6];
    const float* b2     = (const float*)d_in[7];
    const float* Wd     = (const float*)d_in[8];
    const float* bd     = (const float*)d_in[9];
    float* out = (float*)d_out;

    build_xproj_kernel<<<VOCAB / 4, 256>>>(emb, Wx1, b1);

    cudaFuncSetAttribute(rnn_mma_kernel,
                         cudaFuncAttributeMaxDynamicSharedMemorySize, SMEM_NEED);
    rnn_mma_kernel<<<BATCH / MROWS, 256, SMEM_NEED>>>(
        tokens, Wh1, Wx2, Wh2, b2, Wd, bd, out);
}